// round 15
// baseline (speedup 1.0000x reference)
#include <cuda_runtime.h>
#include <cuda_bf16.h>
#include <math.h>
#include <stdint.h>

// ---------------------------------------------------------------------------
// MLA forward. Split-bf16 3-term tensor-core GEMMs (Ah.Bh + Ah.Bl + Al.Bh).
// Round 15: vT produced DIRECTLY by a transposed GEMM
//   vT[b,h][c][t] = wkvb_v[h] . kf[b]^T   (A = weights M=128, B = kf N=2048)
// -> v_eff intermediate + transpose kernel eliminated (536MB traffic).
// k_eff GEMM is k-only now (N=128 into [t][192] buffer + rope fill).
// Round-14 GEMM geometry kept: 128x128 CTA tile, 2x2 warps of 64x64,
// 128 threads, 81.9KB smem (2 CTAs/SM). Fused exp-softmax epilogue with
// deterministic partial sums; causal skipping; de-absorbed attention.
// PTX-stable on compute_103 (no tcgen05).
// ---------------------------------------------------------------------------

#define DIM     2048
#define N_HEADS 16
#define Q_LORA  1536
#define KV_LORA 512
#define NOPE    128
#define ROPE    64
#define V_HEAD  128
#define QK_HEAD 192
#define BATCH   2
#define SEQ     2048
#define ROWS    (BATCH * SEQ)
#define QKD     (KV_LORA + ROPE)        // 576
#define NBH     (BATCH * N_HEADS)       // 32
#define NCOMB   (Q_LORA + QKD)          // 2112
#define KVW     192                     // k row: 128 nope + 64 rope
#define SCALE_F 0.0721687836487032f
#define EPS_F   1e-6f

typedef __nv_bfloat16 bf16;

// ------------------------- scratch (device globals) -------------------------
__device__ __align__(256) bf16  g_xh    [(size_t)ROWS * DIM];
__device__ __align__(256) bf16  g_xl    [(size_t)ROWS * DIM];
__device__ __align__(256) bf16  g_wcombh[(size_t)NCOMB * DIM];
__device__ __align__(256) bf16  g_wcombl[(size_t)NCOMB * DIM];
__device__ __align__(256) bf16  g_wqbh  [(size_t)N_HEADS * QK_HEAD * Q_LORA];
__device__ __align__(256) bf16  g_wqbl  [(size_t)N_HEADS * QK_HEAD * Q_LORA];
__device__ __align__(256) bf16  g_wkvbh [(size_t)N_HEADS * 256 * KV_LORA];
__device__ __align__(256) bf16  g_wkvbl [(size_t)N_HEADS * 256 * KV_LORA];
__device__ __align__(256) bf16  g_woh   [(size_t)DIM * DIM];
__device__ __align__(256) bf16  g_wol   [(size_t)DIM * DIM];

__device__ __align__(256) float g_qakv_f[(size_t)ROWS * NCOMB];
__device__ __align__(256) bf16  g_qah   [(size_t)ROWS * Q_LORA];
__device__ __align__(256) bf16  g_qal   [(size_t)ROWS * Q_LORA];
__device__ __align__(256) bf16  g_qh    [(size_t)ROWS * N_HEADS * QK_HEAD];
__device__ __align__(256) bf16  g_ql    [(size_t)ROWS * N_HEADS * QK_HEAD];
__device__ __align__(256) bf16  g_kfh   [(size_t)ROWS * QKD];
__device__ __align__(256) bf16  g_kfl   [(size_t)ROWS * QKD];

__device__ __align__(256) bf16  g_kveh  [(size_t)NBH * SEQ * KVW];  // [b,h][t][192]
__device__ __align__(256) bf16  g_kvel  [(size_t)NBH * SEQ * KVW];
__device__ __align__(256) bf16  g_vTh   [(size_t)NBH * V_HEAD * SEQ]; // [b,h][c][t]
__device__ __align__(256) bf16  g_vTl   [(size_t)NBH * V_HEAD * SEQ];

__device__ __align__(256) bf16  g_Ph    [(size_t)NBH * SEQ * SEQ];
__device__ __align__(256) bf16  g_Pl    [(size_t)NBH * SEQ * SEQ];
__device__ __align__(256) float g_ps    [(size_t)NBH * SEQ * 16];
__device__ __align__(256) float g_inv   [(size_t)NBH * SEQ];
__device__ __align__(256) bf16  g_o2h   [(size_t)ROWS * DIM];
__device__ __align__(256) bf16  g_o2l   [(size_t)ROWS * DIM];

// ----------------------------- helpers --------------------------------------
__device__ __forceinline__ uint32_t smem_u32(const void* p) {
    uint32_t a;
    asm("{ .reg .u64 t; cvta.to.shared.u64 t, %1; cvt.u32.u64 %0, t; }"
        : "=r"(a) : "l"(p));
    return a;
}
__device__ __forceinline__ void cp16(uint32_t dst, const void* src) {
    asm volatile("cp.async.ca.shared.global [%0], [%1], 16;"
                 :: "r"(dst), "l"(src) : "memory");
}
#define CP_COMMIT() asm volatile("cp.async.commit_group;" ::: "memory")
#define CP_WAIT(n)  asm volatile("cp.async.wait_group %0;" :: "n"(n) : "memory")

__device__ __forceinline__ void ldm_x4(uint32_t* r, uint32_t addr) {
    asm volatile("ldmatrix.sync.aligned.m8n8.x4.shared.b16 {%0,%1,%2,%3}, [%4];"
                 : "=r"(r[0]), "=r"(r[1]), "=r"(r[2]), "=r"(r[3]) : "r"(addr));
}
__device__ __forceinline__ void mma_bf16(float* d, const uint32_t* a,
                                         const uint32_t* b) {
    asm volatile(
        "mma.sync.aligned.m16n8k16.row.col.f32.bf16.bf16.f32 "
        "{%0,%1,%2,%3}, {%4,%5,%6,%7}, {%8,%9}, {%0,%1,%2,%3};"
        : "+f"(d[0]), "+f"(d[1]), "+f"(d[2]), "+f"(d[3])
        : "r"(a[0]), "r"(a[1]), "r"(a[2]), "r"(a[3]), "r"(b[0]), "r"(b[1]));
}
__device__ __forceinline__ void bsplit(float x, bf16& h, bf16& l) {
    h = __float2bfloat16_rn(x);
    l = __float2bfloat16_rn(x - __bfloat162float(h));
}

// ----------------------- GEMM: C = alpha * A.B^T ----------------------------
// CTA tile 128x128, BK=32, 128 threads, warp tile 64x64 (2m x 2n warps).
// OUTM=0: C f32. OUTM=1: split bf16 (C may carry inv-rowsum, mode bit3).
// OUTM=2: exp epilogue -> split bf16 P + per-(row,ntile) partial sums in C.
// mode bit0: causal tile skip (n0 > m0); bit1: causal K bound (m0+128);
// bit3: scale rows by C[row].
#define ROWB 80
#define AT_B (128 * ROWB)                // 10240
#define BT_B (128 * ROWB)                // 10240
#define STG_B (2 * AT_B + 2 * BT_B)      // 40960
#define SMEM_BYTES (2 * STG_B)           // 81920 -> 2 CTAs/SM

__device__ __forceinline__ void load_tileA(uint32_t dst, const bf16* __restrict__ src,
                                           int ld, int k0, int tid) {
#pragma unroll
    for (int it = 0; it < 4; it++) {
        const int idx = tid + it * 128;
        const int row = idx >> 2, seg = idx & 3;
        cp16(dst + (uint32_t)(row * ROWB + seg * 16),
             src + (size_t)row * ld + k0 + seg * 8);
    }
}
__device__ __forceinline__ void load_tileB(uint32_t dst, const bf16* __restrict__ src,
                                           int ld, int k0, int limit, int tid) {
#pragma unroll
    for (int it = 0; it < 4; it++) {
        const int idx = tid + it * 128;
        const int row = idx >> 2, seg = idx & 3;
        const uint32_t d = dst + (uint32_t)(row * ROWB + seg * 16);
        if (row < limit) {
            cp16(d, src + (size_t)row * ld + k0 + seg * 8);
        } else {
            asm volatile("st.shared.v4.b32 [%0], {%1,%1,%1,%1};"
                         :: "r"(d), "r"(0) : "memory");
        }
    }
}
__device__ __forceinline__ void load_stage(uint32_t base,
                                           const bf16* Ath, const bf16* Atl,
                                           const bf16* Bth, const bf16* Btl,
                                           int lda, int ldb, int k0, int nlim, int tid) {
    load_tileA(base,                Ath, lda, k0, tid);
    load_tileA(base + AT_B,         Atl, lda, k0, tid);
    load_tileB(base + 2 * AT_B,        Bth, ldb, k0, nlim, tid);
    load_tileB(base + 2 * AT_B + BT_B, Btl, ldb, k0, nlim, tid);
}

template <int OUTM>
__global__ void __launch_bounds__(128)
gemm_bf3(const bf16* __restrict__ Ah, const bf16* __restrict__ Al,
         const bf16* __restrict__ Bh, const bf16* __restrict__ Bl,
         float* __restrict__ C, bf16* __restrict__ Ch, bf16* __restrict__ Cl,
         int M, int N, int K, int lda, int ldb, int ldc,
         long sAo, long sAi, long sBo, long sBi, long sCo, long sCi,
         int inner, float alpha, int mode)
{
    const int m0 = blockIdx.x * 128, n0 = blockIdx.y * 128;
    if ((mode & 1) && n0 > m0) return;

    extern __shared__ char smem[];
    __shared__ float sred[2][128];
    const uint32_t sb = smem_u32(smem);
    const int tid = threadIdx.x, lane = tid & 31, wid = tid >> 5;
    const int wm = wid >> 1, wn = wid & 1;
    const int g = lane >> 2, tig = lane & 3;

    const int z = blockIdx.z, zo = z / inner, zi = z - zo * inner;
    const long ofA = (long)zo * sAo + (long)zi * sAi;
    const long ofB = (long)zo * sBo + (long)zi * sBi;
    const long ofC = (long)zo * sCo + (long)zi * sCi;
    Ah += ofA; Al += ofA;
    Bh += ofB; Bl += ofB;

    const bf16* Ath = Ah + (size_t)m0 * lda;
    const bf16* Atl = Al + (size_t)m0 * lda;
    const bf16* Bth = Bh + (size_t)n0 * ldb;
    const bf16* Btl = Bl + (size_t)n0 * ldb;
    const int nlim = min(128, N - n0);

    float acc[4][8][4];
#pragma unroll
    for (int i = 0; i < 4; i++)
#pragma unroll
        for (int j = 0; j < 8; j++)
#pragma unroll
            for (int r = 0; r < 4; r++) acc[i][j][r] = 0.f;

    const int Keff = (mode & 2) ? min(K, m0 + 128) : K;
    const int nch = Keff >> 5;

    load_stage(sb, Ath, Atl, Bth, Btl, lda, ldb, 0, nlim, tid);
    CP_COMMIT();

    const uint32_t aoffL = (uint32_t)((wm * 64 + (lane & 15)) * ROWB + (lane >> 4) * 16);
    const uint32_t boffL = (uint32_t)((wn * 64 + ((lane >> 4) & 1) * 8 + (lane & 7)) * ROWB
                                      + ((lane >> 3) & 1) * 16);

    for (int c = 0; c < nch; c++) {
        if (c + 1 < nch) {
            load_stage(sb + ((c + 1) & 1) * STG_B, Ath, Atl, Bth, Btl,
                       lda, ldb, (c + 1) << 5, nlim, tid);
            CP_COMMIT();
            CP_WAIT(1);
        } else {
            CP_WAIT(0);
        }
        __syncthreads();

        const uint32_t base = sb + (c & 1) * STG_B;
        const uint32_t aA = base + aoffL;
        const uint32_t bA = base + 2 * AT_B + boffL;

#pragma unroll
        for (int ks = 0; ks < 2; ks++) {
            uint32_t bh[4][4], bl[4][4];
#pragma unroll
            for (int jj = 0; jj < 4; jj++) {
                ldm_x4(bh[jj], bA + ks * 32 + jj * 16 * ROWB);
                ldm_x4(bl[jj], bA + BT_B + ks * 32 + jj * 16 * ROWB);
            }
#pragma unroll
            for (int i = 0; i < 4; i++) {
                uint32_t ahf[4], alf[4];
                ldm_x4(ahf, aA + ks * 32 + i * 16 * ROWB);
                ldm_x4(alf, aA + AT_B + ks * 32 + i * 16 * ROWB);
#pragma unroll
                for (int j = 0; j < 8; j++) {
                    const uint32_t* bhp = &bh[j >> 1][(j & 1) * 2];
                    const uint32_t* blp = &bl[j >> 1][(j & 1) * 2];
                    mma_bf16(acc[i][j], alf, bhp);
                    mma_bf16(acc[i][j], ahf, blp);
                    mma_bf16(acc[i][j], ahf, bhp);
                }
            }
        }
        __syncthreads();
    }

    if (OUTM == 2) {
        // exp epilogue: unnormalized softmax numerators + deterministic
        // per-(row, n-tile) partial sums. M == SEQ; r0 is the s index.
        float* ps = C + (size_t)z * SEQ * 16;
        const int ntile = n0 >> 7;
#pragma unroll
        for (int i = 0; i < 4; i++) {
            const int r0 = m0 + wm * 64 + i * 16 + g;
            float s0 = 0.f, s1 = 0.f;
#pragma unroll
            for (int j = 0; j < 8; j++) {
                const int col = n0 + wn * 64 + j * 8 + tig * 2;
                const float e0 = (col     <= r0)     ? __expf(alpha * acc[i][j][0]) : 0.f;
                const float e1 = (col + 1 <= r0)     ? __expf(alpha * acc[i][j][1]) : 0.f;
                const float e2 = (col     <= r0 + 8) ? __expf(alpha * acc[i][j][2]) : 0.f;
                const float e3 = (col + 1 <= r0 + 8) ? __expf(alpha * acc[i][j][3]) : 0.f;
                s0 += e0 + e1; s1 += e2 + e3;
                bf16 h0, l0, h1, l1, h2, l2, h3, l3;
                bsplit(e0, h0, l0); bsplit(e1, h1, l1);
                bsplit(e2, h2, l2); bsplit(e3, h3, l3);
                *reinterpret_cast<__nv_bfloat162*>(Ch + ofC + (size_t)r0 * ldc + col)
                    = __nv_bfloat162(h0, h1);
                *reinterpret_cast<__nv_bfloat162*>(Cl + ofC + (size_t)r0 * ldc + col)
                    = __nv_bfloat162(l0, l1);
                *reinterpret_cast<__nv_bfloat162*>(Ch + ofC + (size_t)(r0 + 8) * ldc + col)
                    = __nv_bfloat162(h2, h3);
                *reinterpret_cast<__nv_bfloat162*>(Cl + ofC + (size_t)(r0 + 8) * ldc + col)
                    = __nv_bfloat162(l2, l3);
            }
            s0 += __shfl_xor_sync(0xffffffffu, s0, 1);
            s0 += __shfl_xor_sync(0xffffffffu, s0, 2);
            s1 += __shfl_xor_sync(0xffffffffu, s1, 1);
            s1 += __shfl_xor_sync(0xffffffffu, s1, 2);
            if (tig == 0) {
                sred[wn][wm * 64 + i * 16 + g]     = s0;
                sred[wn][wm * 64 + i * 16 + g + 8] = s1;
            }
        }
        __syncthreads();
        ps[(size_t)(m0 + tid) * 16 + ntile] = sred[0][tid] + sred[1][tid];
        return;
    }

    // standard epilogues
#pragma unroll
    for (int i = 0; i < 4; i++) {
        const int r0 = m0 + wm * 64 + i * 16 + g;
        float sc0 = alpha, sc1 = alpha;
        if (OUTM == 1 && (mode & 8)) {
            const float* invp = C + (size_t)z * SEQ;
            sc0 = invp[r0]; sc1 = invp[r0 + 8];
        }
#pragma unroll
        for (int j = 0; j < 8; j++) {
            const int col = n0 + wn * 64 + j * 8 + tig * 2;
            if (col >= N) continue;
            const float c0 = sc0 * acc[i][j][0], c1 = sc0 * acc[i][j][1];
            const float c2 = sc1 * acc[i][j][2], c3 = sc1 * acc[i][j][3];
            if (OUTM == 0) {
                float* p0 = C + ofC + (size_t)r0 * ldc + col;
                float* p1 = C + ofC + (size_t)(r0 + 8) * ldc + col;
                if (col + 1 < N) {
                    *reinterpret_cast<float2*>(p0) = make_float2(c0, c1);
                    *reinterpret_cast<float2*>(p1) = make_float2(c2, c3);
                } else { p0[0] = c0; p1[0] = c2; }
            } else {
                bf16 h0, l0, h1, l1, h2, l2, h3, l3;
                bsplit(c0, h0, l0); bsplit(c1, h1, l1);
                bsplit(c2, h2, l2); bsplit(c3, h3, l3);
                *reinterpret_cast<__nv_bfloat162*>(Ch + ofC + (size_t)r0 * ldc + col)
                    = __nv_bfloat162(h0, h1);
                *reinterpret_cast<__nv_bfloat162*>(Cl + ofC + (size_t)r0 * ldc + col)
                    = __nv_bfloat162(l0, l1);
                *reinterpret_cast<__nv_bfloat162*>(Ch + ofC + (size_t)(r0 + 8) * ldc + col)
                    = __nv_bfloat162(h2, h3);
                *reinterpret_cast<__nv_bfloat162*>(Cl + ofC + (size_t)(r0 + 8) * ldc + col)
                    = __nv_bfloat162(l2, l3);
            }
        }
    }
}

// ----------------- combine partial sums -> inverse row sums -----------------
__global__ void __launch_bounds__(256)
rowsum_combine_kernel()
{
    const long row = (long)blockIdx.x * 256 + threadIdx.x;  // [bh][s]
    const int s = (int)(row & (SEQ - 1));
    const int nt = (s >> 7) + 1;
    const float* ps = g_ps + row * 16;
    float sum = 0.f;
    for (int j = 0; j < nt; j++) sum += ps[j];
    g_inv[row] = 1.0f / sum;
}

// ---------------------- elementwise split f32 -> bf16 hi/lo ------------------
__global__ void __launch_bounds__(256)
split_kernel(const float* __restrict__ src, bf16* __restrict__ h,
             bf16* __restrict__ l, long n4)
{
    const long stride = (long)gridDim.x * blockDim.x;
    for (long i = blockIdx.x * (long)blockDim.x + threadIdx.x; i < n4; i += stride) {
        const float4 v = reinterpret_cast<const float4*>(src)[i];
        bf16 h0, l0, h1, l1, h2, l2, h3, l3;
        bsplit(v.x, h0, l0); bsplit(v.y, h1, l1);
        bsplit(v.z, h2, l2); bsplit(v.w, h3, l3);
        reinterpret_cast<__nv_bfloat162*>(h)[i * 2]     = __nv_bfloat162(h0, h1);
        reinterpret_cast<__nv_bfloat162*>(h)[i * 2 + 1] = __nv_bfloat162(h2, h3);
        reinterpret_cast<__nv_bfloat162*>(l)[i * 2]     = __nv_bfloat162(l0, l1);
        reinterpret_cast<__nv_bfloat162*>(l)[i * 2 + 1] = __nv_bfloat162(l2, l3);
    }
}

// --------------------------- rmsnorm: f32 -> split --------------------------
__global__ void __launch_bounds__(256)
rmsnorm_qa_kernel(const float* __restrict__ w)
{
    const long row = blockIdx.x;
    const float* p = g_qakv_f + row * NCOMB;
    const int tid = threadIdx.x;
    float v[6];
    float ss = 0.f;
#pragma unroll
    for (int i = 0; i < 6; i++) { v[i] = p[tid + i * 256]; ss += v[i] * v[i]; }
    __shared__ float red[256];
    red[tid] = ss; __syncthreads();
    for (int o = 128; o > 0; o >>= 1) {
        if (tid < o) red[tid] += red[tid + o];
        __syncthreads();
    }
    const float scale = rsqrtf(red[0] / (float)Q_LORA + EPS_F);
#pragma unroll
    for (int i = 0; i < 6; i++) {
        const int c = tid + i * 256;
        bf16 h, l;
        bsplit(v[i] * scale * w[c], h, l);
        g_qah[row * Q_LORA + c] = h;
        g_qal[row * Q_LORA + c] = l;
    }
}

// ------------- kv_process: qakv cols 1536:2112 -> split kf ------------------
__global__ void __launch_bounds__(256)
kv_process_kernel(const float* __restrict__ kv_norm_w,
                  const float* __restrict__ fcos,
                  const float* __restrict__ fsin)
{
    const long row = blockIdx.x;
    const int pos = (int)(row & (SEQ - 1));
    const float* src = g_qakv_f + row * NCOMB + Q_LORA;
    const int tid = threadIdx.x;

    const float v0 = src[tid], v1 = src[tid + 256];
    __shared__ float red[256];
    red[tid] = v0 * v0 + v1 * v1; __syncthreads();
    for (int o = 128; o > 0; o >>= 1) {
        if (tid < o) red[tid] += red[tid + o];
        __syncthreads();
    }
    const float scale = rsqrtf(red[0] / (float)KV_LORA + EPS_F);
    bf16 h, l;
    bsplit(v0 * scale * kv_norm_w[tid], h, l);
    g_kfh[row * QKD + tid] = h; g_kfl[row * QKD + tid] = l;
    bsplit(v1 * scale * kv_norm_w[tid + 256], h, l);
    g_kfh[row * QKD + tid + 256] = h; g_kfl[row * QKD + tid + 256] = l;

    if (tid < 32) {
        const float x0 = src[KV_LORA + 2 * tid];
        const float x1 = src[KV_LORA + 2 * tid + 1];
        const float c = fcos[pos * 32 + tid];
        const float s = fsin[pos * 32 + tid];
        bsplit(x0 * c - x1 * s, h, l);
        g_kfh[row * QKD + KV_LORA + 2 * tid] = h;
        g_kfl[row * QKD + KV_LORA + 2 * tid] = l;
        bsplit(x0 * s + x1 * c, h, l);
        g_kfh[row * QKD + KV_LORA + 2 * tid + 1] = h;
        g_kfl[row * QKD + KV_LORA + 2 * tid + 1] = l;
    }
}

// ------------- q rope (in place on split q) ---------------------------------
__global__ void __launch_bounds__(512)
q_rope_kernel(const float* __restrict__ fcos, const float* __restrict__ fsin)
{
    const long row = blockIdx.x;
    const int pos = (int)(row & (SEQ - 1));
    const int h = threadIdx.x / 32;
    const int i = threadIdx.x % 32;

    const long si = row * (N_HEADS * QK_HEAD) + h * QK_HEAD + NOPE + 2 * i;
    const float x0 = __bfloat162float(g_qh[si])     + __bfloat162float(g_ql[si]);
    const float x1 = __bfloat162float(g_qh[si + 1]) + __bfloat162float(g_ql[si + 1]);
    const float c = fcos[pos * 32 + i];
    const float s = fsin[pos * 32 + i];
    bf16 hh, ll;
    bsplit(x0 * c - x1 * s, hh, ll);
    g_qh[si] = hh; g_ql[si] = ll;
    bsplit(x0 * s + x1 * c, hh, ll);
    g_qh[si + 1] = hh; g_ql[si + 1] = ll;
}

// ------------- broadcast k_pe into kve cols 128:192 -------------------------
__global__ void __launch_bounds__(512)
kpe_fill_kernel()
{
    const long row = blockIdx.x;
    const int b = (int)(row >> 11);
    const int t = (int)(row & (SEQ - 1));
    const long src = row * QKD + KV_LORA;
#pragma unroll
    for (int it = 0; it < 2; it++) {
        const int e = threadIdx.x + it * 512;
        const int h = e >> 6, j = e & 63;
        const long dst = ((long)(b * N_HEADS + h) * SEQ + t) * KVW + NOPE + j;
        g_kveh[dst] = g_kfh[src + j];
        g_kvel[dst] = g_kfl[src + j];
    }
}

// ---------------------------------------------------------------------------
extern "C" void kernel_launch(void* const* d_in, const int* in_sizes, int n_in,
                              void* d_out, int out_size)
{
    const float* x         = (const float*)d_in[0];
    const float* fcos      = (const float*)d_in[1];
    const float* fsin      = (const float*)d_in[2];
    // d_in[3] = mask (unused; causal mask computed inline, exact)
    const float* wq_a      = (const float*)d_in[4];
    const float* q_norm_w  = (const float*)d_in[5];
    const float* wq_b      = (const float*)d_in[6];
    const float* wkv_a     = (const float*)d_in[7];
    const float* kv_norm_w = (const float*)d_in[8];
    const float* wkv_b     = (const float*)d_in[9];
    const float* wo        = (const float*)d_in[10];
    float* out = (float*)d_out;

    bf16 *xh, *xl, *wch, *wcl, *wqbh, *wqbl, *wkvbh, *wkvbl, *woh, *wol;
    bf16 *qah, *qal, *qh, *ql, *kfh, *kfl, *kveh, *kvel, *vTh, *vTl;
    bf16 *Ph, *Pl, *o2h, *o2l;
    float *qakvf, *ps, *inv;
    cudaGetSymbolAddress((void**)&xh, g_xh);       cudaGetSymbolAddress((void**)&xl, g_xl);
    cudaGetSymbolAddress((void**)&wch, g_wcombh);  cudaGetSymbolAddress((void**)&wcl, g_wcombl);
    cudaGetSymbolAddress((void**)&wqbh, g_wqbh);   cudaGetSymbolAddress((void**)&wqbl, g_wqbl);
    cudaGetSymbolAddress((void**)&wkvbh, g_wkvbh); cudaGetSymbolAddress((void**)&wkvbl, g_wkvbl);
    cudaGetSymbolAddress((void**)&woh, g_woh);     cudaGetSymbolAddress((void**)&wol, g_wol);
    cudaGetSymbolAddress((void**)&qakvf, g_qakv_f);
    cudaGetSymbolAddress((void**)&qah, g_qah);     cudaGetSymbolAddress((void**)&qal, g_qal);
    cudaGetSymbolAddress((void**)&qh, g_qh);       cudaGetSymbolAddress((void**)&ql, g_ql);
    cudaGetSymbolAddress((void**)&kfh, g_kfh);     cudaGetSymbolAddress((void**)&kfl, g_kfl);
    cudaGetSymbolAddress((void**)&kveh, g_kveh);   cudaGetSymbolAddress((void**)&kvel, g_kvel);
    cudaGetSymbolAddress((void**)&vTh, g_vTh);     cudaGetSymbolAddress((void**)&vTl, g_vTl);
    cudaGetSymbolAddress((void**)&Ph, g_Ph);       cudaGetSymbolAddress((void**)&Pl, g_Pl);
    cudaGetSymbolAddress((void**)&ps, g_ps);       cudaGetSymbolAddress((void**)&inv, g_inv);
    cudaGetSymbolAddress((void**)&o2h, g_o2h);     cudaGetSymbolAddress((void**)&o2l, g_o2l);

    cudaFuncSetAttribute(gemm_bf3<0>, cudaFuncAttributeMaxDynamicSharedMemorySize, SMEM_BYTES);
    cudaFuncSetAttribute(gemm_bf3<1>, cudaFuncAttributeMaxDynamicSharedMemorySize, SMEM_BYTES);
    cudaFuncSetAttribute(gemm_bf3<2>, cudaFuncAttributeMaxDynamicSharedMemorySize, SMEM_BYTES);

    dim3 blk(256);
    dim3 gblk(128);

    // 0. split inputs + weights
    auto splits = [&](const float* s, bf16* h, bf16* l, long n) {
        const long n4 = n / 4;
        int gs = (int)min((n4 + 255) / 256, (long)4096);
        split_kernel<<<gs, blk>>>(s, h, l, n4);
    };
    splits(x,     xh,  xl,  (long)ROWS * DIM);
    splits(wq_a,  wch, wcl, (long)Q_LORA * DIM);
    splits(wkv_a, wch + (size_t)Q_LORA * DIM, wcl + (size_t)Q_LORA * DIM,
           (long)QKD * DIM);
    splits(wq_b,  wqbh, wqbl, (long)N_HEADS * QK_HEAD * Q_LORA);
    splits(wkv_b, wkvbh, wkvbl, (long)N_HEADS * 256 * KV_LORA);
    splits(wo,    woh,  wol,  (long)DIM * DIM);

    // 1. qakv = x @ [wq_a ; wkv_a]^T  (merged, f32 out)
    gemm_bf3<0><<<dim3(ROWS/128, (NCOMB + 127)/128, 1), gblk, SMEM_BYTES>>>(
        xh, xl, wch, wcl, qakvf, nullptr, nullptr,
        ROWS, NCOMB, DIM, DIM, DIM, NCOMB, 0,0, 0,0, 0,0, 1, 1.f, 0);

    // 2. norms
    rmsnorm_qa_kernel<<<ROWS, blk>>>(q_norm_w);
    kv_process_kernel<<<ROWS, blk>>>(kv_norm_w, fcos, fsin);

    // 3. q = qa @ wq_b^T (split out)
    gemm_bf3<1><<<dim3(ROWS/128, (N_HEADS*QK_HEAD)/128, 1), gblk, SMEM_BYTES>>>(
        qah, qal, wqbh, wqbl, nullptr, qh, ql,
        ROWS, N_HEADS*QK_HEAD, Q_LORA, Q_LORA, Q_LORA, N_HEADS*QK_HEAD,
        0,0, 0,0, 0,0, 1, 1.f, 0);

    // 4. rope(q_pe) in place
    q_rope_kernel<<<ROWS, 512>>>(fcos, fsin);

    // 5a. k_eff[b,h][t][0:128] = kf_c[b] @ wkvb_nope[h]^T  (split, ldc=192)
    gemm_bf3<1><<<dim3(SEQ/128, 1, NBH), gblk, SMEM_BYTES>>>(
        kfh, kfl, wkvbh, wkvbl, nullptr, kveh, kvel,
        SEQ, NOPE, KV_LORA, QKD, KV_LORA, KVW,
        (long)SEQ*QKD, 0,
        0, (long)256*KV_LORA,
        (long)N_HEADS*SEQ*KVW, (long)SEQ*KVW,
        N_HEADS, 1.f, 0);

    // 5b. vT[b,h][c][t] = wkvb_v[h] @ kf_c[b]^T  (transposed GEMM, M=128)
    gemm_bf3<1><<<dim3(1, SEQ/128, NBH), gblk, SMEM_BYTES>>>(
        wkvbh + (size_t)NOPE*KV_LORA, wkvbl + (size_t)NOPE*KV_LORA,
        kfh, kfl, nullptr, vTh, vTl,
        V_HEAD, SEQ, KV_LORA, KV_LORA, QKD, SEQ,
        0, (long)256*KV_LORA,
        (long)SEQ*QKD, 0,
        (long)N_HEADS*V_HEAD*SEQ, (long)V_HEAD*SEQ,
        N_HEADS, 1.f, 0);

    // 6. broadcast k_pe into k cols 128:192
    kpe_fill_kernel<<<ROWS, 512>>>();

    // 7. P~ = exp(SCALE * q'.k^T) (causal, split out + partial sums)
    gemm_bf3<2><<<dim3(SEQ/128, SEQ/128, NBH), gblk, SMEM_BYTES>>>(
        qh, ql, kveh, kvel, ps, Ph, Pl,
        SEQ, SEQ, QK_HEAD, N_HEADS*QK_HEAD, KVW, SEQ,
        (long)SEQ*N_HEADS*QK_HEAD, QK_HEAD,
        (long)N_HEADS*SEQ*KVW, (long)SEQ*KVW,
        (long)N_HEADS*SEQ*SEQ, (long)SEQ*SEQ,
        N_HEADS, SCALE_F, 1);

    // 8. inverse row sums
    rowsum_combine_kernel<<<NBH*SEQ/256, blk>>>();

    // 9. o2 = (P~ @ vT^T) * inv_rowsum  (causal K bound)
    gemm_bf3<1><<<dim3(SEQ/128, 1, NBH), gblk, SMEM_BYTES>>>(
        Ph, Pl, vTh, vTl, inv, o2h, o2l,
        SEQ, V_HEAD, SEQ, SEQ, SEQ, DIM,
        (long)N_HEADS*SEQ*SEQ, (long)SEQ*SEQ,
        (long)N_HEADS*V_HEAD*SEQ, (long)V_HEAD*SEQ,
        (long)SEQ*DIM, V_HEAD,
        N_HEADS, 1.f, 2 | 8);

    // 10. out = o2 @ wo^T  (f32 out)
    gemm_bf3<0><<<dim3(ROWS/128, DIM/128, 1), gblk, SMEM_BYTES>>>(
        o2h, o2l, woh, wol, out, nullptr, nullptr,
        ROWS, DIM, DIM, DIM, DIM, DIM, 0,0, 0,0, 0,0, 1, 1.f, 0);
}

// round 16
// speedup vs baseline: 1.0036x; 1.0036x over previous
#include <cuda_runtime.h>
#include <cuda_bf16.h>
#include <math.h>
#include <stdint.h>

// ---------------------------------------------------------------------------
// MLA forward. Split-bf16 3-term tensor-core GEMMs (Ah.Bh + Ah.Bl + Al.Bh).
// Round 16: round-14 config (best measured) + kpe broadcast folded into
// kv_process (one fewer kernel, kf rope round-trip removed).
// GEMM: 128x128 CTA tile, 2x2 warps of 64x64, 128 threads, 81.9KB smem
// (2 CTAs/SM). Merged qa+kv GEMM, merged k/v GEMM into unified [t][320]
// buffer, fused exp-softmax epilogue with deterministic partial sums,
// causal block skipping, de-absorbed attention.
// PTX-stable on compute_103 (no tcgen05).
// ---------------------------------------------------------------------------

#define DIM     2048
#define N_HEADS 16
#define Q_LORA  1536
#define KV_LORA 512
#define NOPE    128
#define ROPE    64
#define V_HEAD  128
#define QK_HEAD 192
#define BATCH   2
#define SEQ     2048
#define ROWS    (BATCH * SEQ)
#define QKD     (KV_LORA + ROPE)        // 576
#define NBH     (BATCH * N_HEADS)       // 32
#define NCOMB   (Q_LORA + QKD)          // 2112
#define KVW     320                     // 128 nope + 64 rope + 128 v
#define SCALE_F 0.0721687836487032f
#define EPS_F   1e-6f

typedef __nv_bfloat16 bf16;

// ------------------------- scratch (device globals) -------------------------
__device__ __align__(256) bf16  g_xh    [(size_t)ROWS * DIM];
__device__ __align__(256) bf16  g_xl    [(size_t)ROWS * DIM];
__device__ __align__(256) bf16  g_wcombh[(size_t)NCOMB * DIM];
__device__ __align__(256) bf16  g_wcombl[(size_t)NCOMB * DIM];
__device__ __align__(256) bf16  g_wqbh  [(size_t)N_HEADS * QK_HEAD * Q_LORA];
__device__ __align__(256) bf16  g_wqbl  [(size_t)N_HEADS * QK_HEAD * Q_LORA];
__device__ __align__(256) bf16  g_wkvbh [(size_t)N_HEADS * 256 * KV_LORA];
__device__ __align__(256) bf16  g_wkvbl [(size_t)N_HEADS * 256 * KV_LORA];
__device__ __align__(256) bf16  g_woh   [(size_t)DIM * DIM];
__device__ __align__(256) bf16  g_wol   [(size_t)DIM * DIM];

__device__ __align__(256) float g_qakv_f[(size_t)ROWS * NCOMB];
__device__ __align__(256) bf16  g_qah   [(size_t)ROWS * Q_LORA];
__device__ __align__(256) bf16  g_qal   [(size_t)ROWS * Q_LORA];
__device__ __align__(256) bf16  g_qh    [(size_t)ROWS * N_HEADS * QK_HEAD];
__device__ __align__(256) bf16  g_ql    [(size_t)ROWS * N_HEADS * QK_HEAD];
__device__ __align__(256) bf16  g_kfh   [(size_t)ROWS * QKD];
__device__ __align__(256) bf16  g_kfl   [(size_t)ROWS * QKD];

__device__ __align__(256) bf16  g_kveh  [(size_t)NBH * SEQ * KVW];
__device__ __align__(256) bf16  g_kvel  [(size_t)NBH * SEQ * KVW];
__device__ __align__(256) bf16  g_vTh   [(size_t)NBH * V_HEAD * SEQ];
__device__ __align__(256) bf16  g_vTl   [(size_t)NBH * V_HEAD * SEQ];

__device__ __align__(256) bf16  g_Ph    [(size_t)NBH * SEQ * SEQ];
__device__ __align__(256) bf16  g_Pl    [(size_t)NBH * SEQ * SEQ];
__device__ __align__(256) float g_ps    [(size_t)NBH * SEQ * 16];
__device__ __align__(256) float g_inv   [(size_t)NBH * SEQ];
__device__ __align__(256) bf16  g_o2h   [(size_t)ROWS * DIM];
__device__ __align__(256) bf16  g_o2l   [(size_t)ROWS * DIM];

// ----------------------------- helpers --------------------------------------
__device__ __forceinline__ uint32_t smem_u32(const void* p) {
    uint32_t a;
    asm("{ .reg .u64 t; cvta.to.shared.u64 t, %1; cvt.u32.u64 %0, t; }"
        : "=r"(a) : "l"(p));
    return a;
}
__device__ __forceinline__ void cp16(uint32_t dst, const void* src) {
    asm volatile("cp.async.ca.shared.global [%0], [%1], 16;"
                 :: "r"(dst), "l"(src) : "memory");
}
#define CP_COMMIT() asm volatile("cp.async.commit_group;" ::: "memory")
#define CP_WAIT(n)  asm volatile("cp.async.wait_group %0;" :: "n"(n) : "memory")

__device__ __forceinline__ void ldm_x4(uint32_t* r, uint32_t addr) {
    asm volatile("ldmatrix.sync.aligned.m8n8.x4.shared.b16 {%0,%1,%2,%3}, [%4];"
                 : "=r"(r[0]), "=r"(r[1]), "=r"(r[2]), "=r"(r[3]) : "r"(addr));
}
__device__ __forceinline__ void mma_bf16(float* d, const uint32_t* a,
                                         const uint32_t* b) {
    asm volatile(
        "mma.sync.aligned.m16n8k16.row.col.f32.bf16.bf16.f32 "
        "{%0,%1,%2,%3}, {%4,%5,%6,%7}, {%8,%9}, {%0,%1,%2,%3};"
        : "+f"(d[0]), "+f"(d[1]), "+f"(d[2]), "+f"(d[3])
        : "r"(a[0]), "r"(a[1]), "r"(a[2]), "r"(a[3]), "r"(b[0]), "r"(b[1]));
}
__device__ __forceinline__ void bsplit(float x, bf16& h, bf16& l) {
    h = __float2bfloat16_rn(x);
    l = __float2bfloat16_rn(x - __bfloat162float(h));
}

// ----------------------- GEMM: C = alpha * A.B^T ----------------------------
// CTA tile 128x128, BK=32, 128 threads, warp tile 64x64 (2m x 2n warps).
// OUTM=0: C f32. OUTM=1: split bf16 (C may carry inv-rowsum, mode bit3).
// OUTM=2: exp epilogue -> split bf16 P + per-(row,ntile) partial sums in C.
// mode bit0: causal tile skip (n0 > m0); bit1: causal K bound (m0+128);
// bit2: col+=64 if col>=128 (unified k/v layout); bit3: scale rows by C[row].
#define ROWB 80
#define AT_B (128 * ROWB)                // 10240
#define BT_B (128 * ROWB)                // 10240
#define STG_B (2 * AT_B + 2 * BT_B)      // 40960
#define SMEM_BYTES (2 * STG_B)           // 81920 -> 2 CTAs/SM

__device__ __forceinline__ void load_tileA(uint32_t dst, const bf16* __restrict__ src,
                                           int ld, int k0, int tid) {
#pragma unroll
    for (int it = 0; it < 4; it++) {
        const int idx = tid + it * 128;
        const int row = idx >> 2, seg = idx & 3;
        cp16(dst + (uint32_t)(row * ROWB + seg * 16),
             src + (size_t)row * ld + k0 + seg * 8);
    }
}
__device__ __forceinline__ void load_tileB(uint32_t dst, const bf16* __restrict__ src,
                                           int ld, int k0, int limit, int tid) {
#pragma unroll
    for (int it = 0; it < 4; it++) {
        const int idx = tid + it * 128;
        const int row = idx >> 2, seg = idx & 3;
        const uint32_t d = dst + (uint32_t)(row * ROWB + seg * 16);
        if (row < limit) {
            cp16(d, src + (size_t)row * ld + k0 + seg * 8);
        } else {
            asm volatile("st.shared.v4.b32 [%0], {%1,%1,%1,%1};"
                         :: "r"(d), "r"(0) : "memory");
        }
    }
}
__device__ __forceinline__ void load_stage(uint32_t base,
                                           const bf16* Ath, const bf16* Atl,
                                           const bf16* Bth, const bf16* Btl,
                                           int lda, int ldb, int k0, int nlim, int tid) {
    load_tileA(base,                Ath, lda, k0, tid);
    load_tileA(base + AT_B,         Atl, lda, k0, tid);
    load_tileB(base + 2 * AT_B,        Bth, ldb, k0, nlim, tid);
    load_tileB(base + 2 * AT_B + BT_B, Btl, ldb, k0, nlim, tid);
}

template <int OUTM>
__global__ void __launch_bounds__(128)
gemm_bf3(const bf16* __restrict__ Ah, const bf16* __restrict__ Al,
         const bf16* __restrict__ Bh, const bf16* __restrict__ Bl,
         float* __restrict__ C, bf16* __restrict__ Ch, bf16* __restrict__ Cl,
         int M, int N, int K, int lda, int ldb, int ldc,
         long sAo, long sAi, long sBo, long sBi, long sCo, long sCi,
         int inner, float alpha, int mode)
{
    const int m0 = blockIdx.x * 128, n0 = blockIdx.y * 128;
    if ((mode & 1) && n0 > m0) return;

    extern __shared__ char smem[];
    __shared__ float sred[2][128];
    const uint32_t sb = smem_u32(smem);
    const int tid = threadIdx.x, lane = tid & 31, wid = tid >> 5;
    const int wm = wid >> 1, wn = wid & 1;
    const int g = lane >> 2, tig = lane & 3;

    const int z = blockIdx.z, zo = z / inner, zi = z - zo * inner;
    const long ofA = (long)zo * sAo + (long)zi * sAi;
    const long ofB = (long)zo * sBo + (long)zi * sBi;
    const long ofC = (long)zo * sCo + (long)zi * sCi;
    Ah += ofA; Al += ofA;
    Bh += ofB; Bl += ofB;

    const bf16* Ath = Ah + (size_t)m0 * lda;
    const bf16* Atl = Al + (size_t)m0 * lda;
    const bf16* Bth = Bh + (size_t)n0 * ldb;
    const bf16* Btl = Bl + (size_t)n0 * ldb;
    const int nlim = min(128, N - n0);

    float acc[4][8][4];
#pragma unroll
    for (int i = 0; i < 4; i++)
#pragma unroll
        for (int j = 0; j < 8; j++)
#pragma unroll
            for (int r = 0; r < 4; r++) acc[i][j][r] = 0.f;

    const int Keff = (mode & 2) ? min(K, m0 + 128) : K;
    const int nch = Keff >> 5;

    load_stage(sb, Ath, Atl, Bth, Btl, lda, ldb, 0, nlim, tid);
    CP_COMMIT();

    const uint32_t aoffL = (uint32_t)((wm * 64 + (lane & 15)) * ROWB + (lane >> 4) * 16);
    const uint32_t boffL = (uint32_t)((wn * 64 + ((lane >> 4) & 1) * 8 + (lane & 7)) * ROWB
                                      + ((lane >> 3) & 1) * 16);

    for (int c = 0; c < nch; c++) {
        if (c + 1 < nch) {
            load_stage(sb + ((c + 1) & 1) * STG_B, Ath, Atl, Bth, Btl,
                       lda, ldb, (c + 1) << 5, nlim, tid);
            CP_COMMIT();
            CP_WAIT(1);
        } else {
            CP_WAIT(0);
        }
        __syncthreads();

        const uint32_t base = sb + (c & 1) * STG_B;
        const uint32_t aA = base + aoffL;
        const uint32_t bA = base + 2 * AT_B + boffL;

#pragma unroll
        for (int ks = 0; ks < 2; ks++) {
            uint32_t bh[4][4], bl[4][4];
#pragma unroll
            for (int jj = 0; jj < 4; jj++) {
                ldm_x4(bh[jj], bA + ks * 32 + jj * 16 * ROWB);
                ldm_x4(bl[jj], bA + BT_B + ks * 32 + jj * 16 * ROWB);
            }
#pragma unroll
            for (int i = 0; i < 4; i++) {
                uint32_t ahf[4], alf[4];
                ldm_x4(ahf, aA + ks * 32 + i * 16 * ROWB);
                ldm_x4(alf, aA + AT_B + ks * 32 + i * 16 * ROWB);
#pragma unroll
                for (int j = 0; j < 8; j++) {
                    const uint32_t* bhp = &bh[j >> 1][(j & 1) * 2];
                    const uint32_t* blp = &bl[j >> 1][(j & 1) * 2];
                    mma_bf16(acc[i][j], alf, bhp);
                    mma_bf16(acc[i][j], ahf, blp);
                    mma_bf16(acc[i][j], ahf, bhp);
                }
            }
        }
        __syncthreads();
    }

    if (OUTM == 2) {
        // exp epilogue: unnormalized softmax numerators + deterministic
        // per-(row, n-tile) partial sums. M == SEQ; r0 is the s index.
        float* ps = C + (size_t)z * SEQ * 16;
        const int ntile = n0 >> 7;
#pragma unroll
        for (int i = 0; i < 4; i++) {
            const int r0 = m0 + wm * 64 + i * 16 + g;
            float s0 = 0.f, s1 = 0.f;
#pragma unroll
            for (int j = 0; j < 8; j++) {
                const int col = n0 + wn * 64 + j * 8 + tig * 2;
                const float e0 = (col     <= r0)     ? __expf(alpha * acc[i][j][0]) : 0.f;
                const float e1 = (col + 1 <= r0)     ? __expf(alpha * acc[i][j][1]) : 0.f;
                const float e2 = (col     <= r0 + 8) ? __expf(alpha * acc[i][j][2]) : 0.f;
                const float e3 = (col + 1 <= r0 + 8) ? __expf(alpha * acc[i][j][3]) : 0.f;
                s0 += e0 + e1; s1 += e2 + e3;
                bf16 h0, l0, h1, l1, h2, l2, h3, l3;
                bsplit(e0, h0, l0); bsplit(e1, h1, l1);
                bsplit(e2, h2, l2); bsplit(e3, h3, l3);
                *reinterpret_cast<__nv_bfloat162*>(Ch + ofC + (size_t)r0 * ldc + col)
                    = __nv_bfloat162(h0, h1);
                *reinterpret_cast<__nv_bfloat162*>(Cl + ofC + (size_t)r0 * ldc + col)
                    = __nv_bfloat162(l0, l1);
                *reinterpret_cast<__nv_bfloat162*>(Ch + ofC + (size_t)(r0 + 8) * ldc + col)
                    = __nv_bfloat162(h2, h3);
                *reinterpret_cast<__nv_bfloat162*>(Cl + ofC + (size_t)(r0 + 8) * ldc + col)
                    = __nv_bfloat162(l2, l3);
            }
            s0 += __shfl_xor_sync(0xffffffffu, s0, 1);
            s0 += __shfl_xor_sync(0xffffffffu, s0, 2);
            s1 += __shfl_xor_sync(0xffffffffu, s1, 1);
            s1 += __shfl_xor_sync(0xffffffffu, s1, 2);
            if (tig == 0) {
                sred[wn][wm * 64 + i * 16 + g]     = s0;
                sred[wn][wm * 64 + i * 16 + g + 8] = s1;
            }
        }
        __syncthreads();
        ps[(size_t)(m0 + tid) * 16 + ntile] = sred[0][tid] + sred[1][tid];
        return;
    }

    // standard epilogues
#pragma unroll
    for (int i = 0; i < 4; i++) {
        const int r0 = m0 + wm * 64 + i * 16 + g;
        float sc0 = alpha, sc1 = alpha;
        if (OUTM == 1 && (mode & 8)) {
            const float* invp = C + (size_t)z * SEQ;
            sc0 = invp[r0]; sc1 = invp[r0 + 8];
        }
#pragma unroll
        for (int j = 0; j < 8; j++) {
            const int col = n0 + wn * 64 + j * 8 + tig * 2;
            if (col >= N) continue;
            const int ocol = ((mode & 4) && col >= 128) ? col + 64 : col;
            const float c0 = sc0 * acc[i][j][0], c1 = sc0 * acc[i][j][1];
            const float c2 = sc1 * acc[i][j][2], c3 = sc1 * acc[i][j][3];
            if (OUTM == 0) {
                float* p0 = C + ofC + (size_t)r0 * ldc + ocol;
                float* p1 = C + ofC + (size_t)(r0 + 8) * ldc + ocol;
                if (col + 1 < N) {
                    *reinterpret_cast<float2*>(p0) = make_float2(c0, c1);
                    *reinterpret_cast<float2*>(p1) = make_float2(c2, c3);
                } else { p0[0] = c0; p1[0] = c2; }
            } else {
                bf16 h0, l0, h1, l1, h2, l2, h3, l3;
                bsplit(c0, h0, l0); bsplit(c1, h1, l1);
                bsplit(c2, h2, l2); bsplit(c3, h3, l3);
                *reinterpret_cast<__nv_bfloat162*>(Ch + ofC + (size_t)r0 * ldc + ocol)
                    = __nv_bfloat162(h0, h1);
                *reinterpret_cast<__nv_bfloat162*>(Cl + ofC + (size_t)r0 * ldc + ocol)
                    = __nv_bfloat162(l0, l1);
                *reinterpret_cast<__nv_bfloat162*>(Ch + ofC + (size_t)(r0 + 8) * ldc + ocol)
                    = __nv_bfloat162(h2, h3);
                *reinterpret_cast<__nv_bfloat162*>(Cl + ofC + (size_t)(r0 + 8) * ldc + ocol)
                    = __nv_bfloat162(l2, l3);
            }
        }
    }
}

// ----------------- combine partial sums -> inverse row sums -----------------
__global__ void __launch_bounds__(256)
rowsum_combine_kernel()
{
    const long row = (long)blockIdx.x * 256 + threadIdx.x;  // [bh][s]
    const int s = (int)(row & (SEQ - 1));
    const int nt = (s >> 7) + 1;
    const float* ps = g_ps + row * 16;
    float sum = 0.f;
    for (int j = 0; j < nt; j++) sum += ps[j];
    g_inv[row] = 1.0f / sum;
}

// ---------------------- elementwise split f32 -> bf16 hi/lo ------------------
__global__ void __launch_bounds__(256)
split_kernel(const float* __restrict__ src, bf16* __restrict__ h,
             bf16* __restrict__ l, long n4)
{
    const long stride = (long)gridDim.x * blockDim.x;
    for (long i = blockIdx.x * (long)blockDim.x + threadIdx.x; i < n4; i += stride) {
        const float4 v = reinterpret_cast<const float4*>(src)[i];
        bf16 h0, l0, h1, l1, h2, l2, h3, l3;
        bsplit(v.x, h0, l0); bsplit(v.y, h1, l1);
        bsplit(v.z, h2, l2); bsplit(v.w, h3, l3);
        reinterpret_cast<__nv_bfloat162*>(h)[i * 2]     = __nv_bfloat162(h0, h1);
        reinterpret_cast<__nv_bfloat162*>(h)[i * 2 + 1] = __nv_bfloat162(h2, h3);
        reinterpret_cast<__nv_bfloat162*>(l)[i * 2]     = __nv_bfloat162(l0, l1);
        reinterpret_cast<__nv_bfloat162*>(l)[i * 2 + 1] = __nv_bfloat162(l2, l3);
    }
}

// ------------------- dual bf16 transpose (32x32 tiles) ----------------------
__global__ void __launch_bounds__(256)
transpose_bf2(const bf16* __restrict__ sh, const bf16* __restrict__ sl,
              bf16* __restrict__ dh, bf16* __restrict__ dl,
              int lds, int ldd, long sS, long sD)
{
    __shared__ float th[32][33], tl[32][33];
    const int z = blockIdx.z;
    sh += (long)z * sS; sl += (long)z * sS;
    dh += (long)z * sD; dl += (long)z * sD;
    const int r0 = blockIdx.x * 32, c0 = blockIdx.y * 32;
    const int tx = threadIdx.x, ty = threadIdx.y;
#pragma unroll
    for (int i = 0; i < 4; i++) {
        const long s = (long)(r0 + ty + 8 * i) * lds + c0 + tx;
        th[ty + 8 * i][tx] = __bfloat162float(sh[s]);
        tl[ty + 8 * i][tx] = __bfloat162float(sl[s]);
    }
    __syncthreads();
#pragma unroll
    for (int i = 0; i < 4; i++) {
        const long d = (long)(c0 + ty + 8 * i) * ldd + r0 + tx;
        dh[d] = __float2bfloat16_rn(th[tx][ty + 8 * i]);
        dl[d] = __float2bfloat16_rn(tl[tx][ty + 8 * i]);
    }
}

// --------------------------- rmsnorm: f32 -> split --------------------------
__global__ void __launch_bounds__(256)
rmsnorm_qa_kernel(const float* __restrict__ w)
{
    const long row = blockIdx.x;
    const float* p = g_qakv_f + row * NCOMB;
    const int tid = threadIdx.x;
    float v[6];
    float ss = 0.f;
#pragma unroll
    for (int i = 0; i < 6; i++) { v[i] = p[tid + i * 256]; ss += v[i] * v[i]; }
    __shared__ float red[256];
    red[tid] = ss; __syncthreads();
    for (int o = 128; o > 0; o >>= 1) {
        if (tid < o) red[tid] += red[tid + o];
        __syncthreads();
    }
    const float scale = rsqrtf(red[0] / (float)Q_LORA + EPS_F);
#pragma unroll
    for (int i = 0; i < 6; i++) {
        const int c = tid + i * 256;
        bf16 h, l;
        bsplit(v[i] * scale * w[c], h, l);
        g_qah[row * Q_LORA + c] = h;
        g_qal[row * Q_LORA + c] = l;
    }
}

// ------------- kv_process: qakv cols 1536:2112 -> split kf + rope broadcast --
// Writes the normed kv_cache into kf (cols 0:512), and the rope(k_pe) values
// DIRECTLY into all N_HEADS kve slots (cols 128:192) -- kpe_fill eliminated.
__global__ void __launch_bounds__(256)
kv_process_kernel(const float* __restrict__ kv_norm_w,
                  const float* __restrict__ fcos,
                  const float* __restrict__ fsin)
{
    const long row = blockIdx.x;
    const int b = (int)(row >> 11);
    const int pos = (int)(row & (SEQ - 1));
    const float* src = g_qakv_f + row * NCOMB + Q_LORA;
    const int tid = threadIdx.x;

    __shared__ float red[256];
    __shared__ bf16 rh[ROPE], rl[ROPE];

    const float v0 = src[tid], v1 = src[tid + 256];
    red[tid] = v0 * v0 + v1 * v1; __syncthreads();
    for (int o = 128; o > 0; o >>= 1) {
        if (tid < o) red[tid] += red[tid + o];
        __syncthreads();
    }
    const float scale = rsqrtf(red[0] / (float)KV_LORA + EPS_F);
    bf16 h, l;
    bsplit(v0 * scale * kv_norm_w[tid], h, l);
    g_kfh[row * QKD + tid] = h; g_kfl[row * QKD + tid] = l;
    bsplit(v1 * scale * kv_norm_w[tid + 256], h, l);
    g_kfh[row * QKD + tid + 256] = h; g_kfl[row * QKD + tid + 256] = l;

    if (tid < 32) {
        const float x0 = src[KV_LORA + 2 * tid];
        const float x1 = src[KV_LORA + 2 * tid + 1];
        const float c = fcos[pos * 32 + tid];
        const float s = fsin[pos * 32 + tid];
        bsplit(x0 * c - x1 * s, h, l);
        rh[2 * tid] = h; rl[2 * tid] = l;
        bsplit(x0 * s + x1 * c, h, l);
        rh[2 * tid + 1] = h; rl[2 * tid + 1] = l;
    }
    __syncthreads();

    // broadcast rope into kve cols 128:192 for all heads (1024 positions)
#pragma unroll
    for (int it = 0; it < 4; it++) {
        const int e = tid + it * 256;            // 0..1023
        const int hd = e >> 6, j = e & 63;
        const size_t dst = ((size_t)(b * N_HEADS + hd) * SEQ + pos) * KVW + NOPE + j;
        g_kveh[dst] = rh[j];
        g_kvel[dst] = rl[j];
    }
}

// ------------- q rope (in place on split q) ---------------------------------
__global__ void __launch_bounds__(512)
q_rope_kernel(const float* __restrict__ fcos, const float* __restrict__ fsin)
{
    const long row = blockIdx.x;
    const int pos = (int)(row & (SEQ - 1));
    const int h = threadIdx.x / 32;
    const int i = threadIdx.x % 32;

    const long si = row * (N_HEADS * QK_HEAD) + h * QK_HEAD + NOPE + 2 * i;
    const float x0 = __bfloat162float(g_qh[si])     + __bfloat162float(g_ql[si]);
    const float x1 = __bfloat162float(g_qh[si + 1]) + __bfloat162float(g_ql[si + 1]);
    const float c = fcos[pos * 32 + i];
    const float s = fsin[pos * 32 + i];
    bf16 hh, ll;
    bsplit(x0 * c - x1 * s, hh, ll);
    g_qh[si] = hh; g_ql[si] = ll;
    bsplit(x0 * s + x1 * c, hh, ll);
    g_qh[si + 1] = hh; g_ql[si + 1] = ll;
}

// ---------------------------------------------------------------------------
extern "C" void kernel_launch(void* const* d_in, const int* in_sizes, int n_in,
                              void* d_out, int out_size)
{
    const float* x         = (const float*)d_in[0];
    const float* fcos      = (const float*)d_in[1];
    const float* fsin      = (const float*)d_in[2];
    // d_in[3] = mask (unused; causal mask computed inline, exact)
    const float* wq_a      = (const float*)d_in[4];
    const float* q_norm_w  = (const float*)d_in[5];
    const float* wq_b      = (const float*)d_in[6];
    const float* wkv_a     = (const float*)d_in[7];
    const float* kv_norm_w = (const float*)d_in[8];
    const float* wkv_b     = (const float*)d_in[9];
    const float* wo        = (const float*)d_in[10];
    float* out = (float*)d_out;

    bf16 *xh, *xl, *wch, *wcl, *wqbh, *wqbl, *wkvbh, *wkvbl, *woh, *wol;
    bf16 *qah, *qal, *qh, *ql, *kfh, *kfl, *kveh, *kvel, *vTh, *vTl;
    bf16 *Ph, *Pl, *o2h, *o2l;
    float *qakvf, *ps, *inv;
    cudaGetSymbolAddress((void**)&xh, g_xh);       cudaGetSymbolAddress((void**)&xl, g_xl);
    cudaGetSymbolAddress((void**)&wch, g_wcombh);  cudaGetSymbolAddress((void**)&wcl, g_wcombl);
    cudaGetSymbolAddress((void**)&wqbh, g_wqbh);   cudaGetSymbolAddress((void**)&wqbl, g_wqbl);
    cudaGetSymbolAddress((void**)&wkvbh, g_wkvbh); cudaGetSymbolAddress((void**)&wkvbl, g_wkvbl);
    cudaGetSymbolAddress((void**)&woh, g_woh);     cudaGetSymbolAddress((void**)&wol, g_wol);
    cudaGetSymbolAddress((void**)&qakvf, g_qakv_f);
    cudaGetSymbolAddress((void**)&qah, g_qah);     cudaGetSymbolAddress((void**)&qal, g_qal);
    cudaGetSymbolAddress((void**)&qh, g_qh);       cudaGetSymbolAddress((void**)&ql, g_ql);
    cudaGetSymbolAddress((void**)&kfh, g_kfh);     cudaGetSymbolAddress((void**)&kfl, g_kfl);
    cudaGetSymbolAddress((void**)&kveh, g_kveh);   cudaGetSymbolAddress((void**)&kvel, g_kvel);
    cudaGetSymbolAddress((void**)&vTh, g_vTh);     cudaGetSymbolAddress((void**)&vTl, g_vTl);
    cudaGetSymbolAddress((void**)&Ph, g_Ph);       cudaGetSymbolAddress((void**)&Pl, g_Pl);
    cudaGetSymbolAddress((void**)&ps, g_ps);       cudaGetSymbolAddress((void**)&inv, g_inv);
    cudaGetSymbolAddress((void**)&o2h, g_o2h);     cudaGetSymbolAddress((void**)&o2l, g_o2l);

    cudaFuncSetAttribute(gemm_bf3<0>, cudaFuncAttributeMaxDynamicSharedMemorySize, SMEM_BYTES);
    cudaFuncSetAttribute(gemm_bf3<1>, cudaFuncAttributeMaxDynamicSharedMemorySize, SMEM_BYTES);
    cudaFuncSetAttribute(gemm_bf3<2>, cudaFuncAttributeMaxDynamicSharedMemorySize, SMEM_BYTES);

    dim3 blk(256);
    dim3 gblk(128);
    dim3 tb(32, 8);

    // 0. split inputs + weights
    auto splits = [&](const float* s, bf16* h, bf16* l, long n) {
        const long n4 = n / 4;
        int gs = (int)min((n4 + 255) / 256, (long)4096);
        split_kernel<<<gs, blk>>>(s, h, l, n4);
    };
    splits(x,     xh,  xl,  (long)ROWS * DIM);
    splits(wq_a,  wch, wcl, (long)Q_LORA * DIM);
    splits(wkv_a, wch + (size_t)Q_LORA * DIM, wcl + (size_t)Q_LORA * DIM,
           (long)QKD * DIM);
    splits(wq_b,  wqbh, wqbl, (long)N_HEADS * QK_HEAD * Q_LORA);
    splits(wkv_b, wkvbh, wkvbl, (long)N_HEADS * 256 * KV_LORA);
    splits(wo,    woh,  wol,  (long)DIM * DIM);

    // 1. qakv = x @ [wq_a ; wkv_a]^T  (merged, f32 out)
    gemm_bf3<0><<<dim3(ROWS/128, (NCOMB + 127)/128, 1), gblk, SMEM_BYTES>>>(
        xh, xl, wch, wcl, qakvf, nullptr, nullptr,
        ROWS, NCOMB, DIM, DIM, DIM, NCOMB, 0,0, 0,0, 0,0, 1, 1.f, 0);

    // 2. norms (+ rope broadcast into kve)
    rmsnorm_qa_kernel<<<ROWS, blk>>>(q_norm_w);
    kv_process_kernel<<<ROWS, blk>>>(kv_norm_w, fcos, fsin);

    // 3. q = qa @ wq_b^T (split out)
    gemm_bf3<1><<<dim3(ROWS/128, (N_HEADS*QK_HEAD)/128, 1), gblk, SMEM_BYTES>>>(
        qah, qal, wqbh, wqbl, nullptr, qh, ql,
        ROWS, N_HEADS*QK_HEAD, Q_LORA, Q_LORA, Q_LORA, N_HEADS*QK_HEAD,
        0,0, 0,0, 0,0, 1, 1.f, 0);

    // 4. rope(q_pe) in place
    q_rope_kernel<<<ROWS, 512>>>(fcos, fsin);

    // 5. kve = kf_c @ wkvb^T  (merged k/v, split out, col shift)
    gemm_bf3<1><<<dim3(SEQ/128, 2, NBH), gblk, SMEM_BYTES>>>(
        kfh, kfl, wkvbh, wkvbl, nullptr, kveh, kvel,
        SEQ, 256, KV_LORA, QKD, KV_LORA, KVW,
        (long)SEQ*QKD, 0,
        0, (long)256*KV_LORA,
        (long)N_HEADS*SEQ*KVW, (long)SEQ*KVW,
        N_HEADS, 1.f, 4);

    // 6. transpose v (kve cols 192:320) -> vT
    transpose_bf2<<<dim3(SEQ/32, V_HEAD/32, NBH), tb>>>(
        kveh + 192, kvel + 192, vTh, vTl, KVW, SEQ,
        (long)SEQ*KVW, (long)V_HEAD*SEQ);

    // 7. P~ = exp(SCALE * q'.kve^T) (causal, split out + partial sums)
    gemm_bf3<2><<<dim3(SEQ/128, SEQ/128, NBH), gblk, SMEM_BYTES>>>(
        qh, ql, kveh, kvel, ps, Ph, Pl,
        SEQ, SEQ, QK_HEAD, N_HEADS*QK_HEAD, KVW, SEQ,
        (long)SEQ*N_HEADS*QK_HEAD, QK_HEAD,
        (long)N_HEADS*SEQ*KVW, (long)SEQ*KVW,
        (long)N_HEADS*SEQ*SEQ, (long)SEQ*SEQ,
        N_HEADS, SCALE_F, 1);

    // 8. inverse row sums (deterministic fixed-order combine)
    rowsum_combine_kernel<<<NBH*SEQ/256, blk>>>();

    // 9. o2 = (P~ @ vT^T) * inv_rowsum  (causal K bound)
    gemm_bf3<1><<<dim3(SEQ/128, 1, NBH), gblk, SMEM_BYTES>>>(
        Ph, Pl, vTh, vTl, inv, o2h, o2l,
        SEQ, V_HEAD, SEQ, SEQ, SEQ, DIM,
        (long)N_HEADS*SEQ*SEQ, (long)SEQ*SEQ,
        (long)N_HEADS*V_HEAD*SEQ, (long)V_HEAD*SEQ,
        (long)SEQ*DIM, V_HEAD,
        N_HEADS, 1.f, 2 | 8);

    // 10. out = o2 @ wo^T  (f32 out)
    gemm_bf3<0><<<dim3(ROWS/128, DIM/128, 1), gblk, SMEM_BYTES>>>(
        o2h, o2l, woh, wol, out, nullptr, nullptr,
        ROWS, DIM, DIM, DIM, DIM, DIM, 0,0, 0,0, 0,0, 1, 1.f, 0);
}

// round 17
// speedup vs baseline: 1.0327x; 1.0290x over previous
#include <cuda_runtime.h>
#include <cuda_bf16.h>
#include <math.h>
#include <stdint.h>

// ---------------------------------------------------------------------------
// MLA forward. Split-bf16 3-term tensor-core GEMMs (Ah.Bh + Ah.Bl + Al.Bh).
// Round 17 (on round-16 base):
//  - q rope fused into the q-GEMM epilogue (each thread already holds the
//    even/odd column pair) -- q_rope kernel + 100MB round-trip deleted.
//  - P.V GEMM launches longest-K CTAs first (reverse-m) for wave packing.
//  - scores grid compacted to the 136 live causal tiles per z.
// GEMM: 128x128 CTA tile, 2x2 warps of 64x64, 128 threads, 81.9KB smem
// (2 CTAs/SM). Merged qa+kv GEMM, merged k/v GEMM with rope broadcast in
// kv_process, fused exp-softmax epilogue with deterministic partial sums,
// de-absorbed attention. PTX-stable on compute_103 (no tcgen05).
// ---------------------------------------------------------------------------

#define DIM     2048
#define N_HEADS 16
#define Q_LORA  1536
#define KV_LORA 512
#define NOPE    128
#define ROPE    64
#define V_HEAD  128
#define QK_HEAD 192
#define BATCH   2
#define SEQ     2048
#define ROWS    (BATCH * SEQ)
#define QKD     (KV_LORA + ROPE)        // 576
#define NBH     (BATCH * N_HEADS)       // 32
#define NCOMB   (Q_LORA + QKD)          // 2112
#define KVW     320                     // 128 nope + 64 rope + 128 v
#define SCALE_F 0.0721687836487032f
#define EPS_F   1e-6f
#define NTRI    136                     // 16*17/2 causal tiles per z

typedef __nv_bfloat16 bf16;

// ------------------------- scratch (device globals) -------------------------
__device__ __align__(256) bf16  g_xh    [(size_t)ROWS * DIM];
__device__ __align__(256) bf16  g_xl    [(size_t)ROWS * DIM];
__device__ __align__(256) bf16  g_wcombh[(size_t)NCOMB * DIM];
__device__ __align__(256) bf16  g_wcombl[(size_t)NCOMB * DIM];
__device__ __align__(256) bf16  g_wqbh  [(size_t)N_HEADS * QK_HEAD * Q_LORA];
__device__ __align__(256) bf16  g_wqbl  [(size_t)N_HEADS * QK_HEAD * Q_LORA];
__device__ __align__(256) bf16  g_wkvbh [(size_t)N_HEADS * 256 * KV_LORA];
__device__ __align__(256) bf16  g_wkvbl [(size_t)N_HEADS * 256 * KV_LORA];
__device__ __align__(256) bf16  g_woh   [(size_t)DIM * DIM];
__device__ __align__(256) bf16  g_wol   [(size_t)DIM * DIM];

__device__ __align__(256) float g_qakv_f[(size_t)ROWS * NCOMB];
__device__ __align__(256) bf16  g_qah   [(size_t)ROWS * Q_LORA];
__device__ __align__(256) bf16  g_qal   [(size_t)ROWS * Q_LORA];
__device__ __align__(256) bf16  g_qh    [(size_t)ROWS * N_HEADS * QK_HEAD];
__device__ __align__(256) bf16  g_ql    [(size_t)ROWS * N_HEADS * QK_HEAD];
__device__ __align__(256) bf16  g_kfh   [(size_t)ROWS * QKD];
__device__ __align__(256) bf16  g_kfl   [(size_t)ROWS * QKD];

__device__ __align__(256) bf16  g_kveh  [(size_t)NBH * SEQ * KVW];
__device__ __align__(256) bf16  g_kvel  [(size_t)NBH * SEQ * KVW];
__device__ __align__(256) bf16  g_vTh   [(size_t)NBH * V_HEAD * SEQ];
__device__ __align__(256) bf16  g_vTl   [(size_t)NBH * V_HEAD * SEQ];

__device__ __align__(256) bf16  g_Ph    [(size_t)NBH * SEQ * SEQ];
__device__ __align__(256) bf16  g_Pl    [(size_t)NBH * SEQ * SEQ];
__device__ __align__(256) float g_ps    [(size_t)NBH * SEQ * 16];
__device__ __align__(256) float g_inv   [(size_t)NBH * SEQ];
__device__ __align__(256) bf16  g_o2h   [(size_t)ROWS * DIM];
__device__ __align__(256) bf16  g_o2l   [(size_t)ROWS * DIM];

// ----------------------------- helpers --------------------------------------
__device__ __forceinline__ uint32_t smem_u32(const void* p) {
    uint32_t a;
    asm("{ .reg .u64 t; cvta.to.shared.u64 t, %1; cvt.u32.u64 %0, t; }"
        : "=r"(a) : "l"(p));
    return a;
}
__device__ __forceinline__ void cp16(uint32_t dst, const void* src) {
    asm volatile("cp.async.ca.shared.global [%0], [%1], 16;"
                 :: "r"(dst), "l"(src) : "memory");
}
#define CP_COMMIT() asm volatile("cp.async.commit_group;" ::: "memory")
#define CP_WAIT(n)  asm volatile("cp.async.wait_group %0;" :: "n"(n) : "memory")

__device__ __forceinline__ void ldm_x4(uint32_t* r, uint32_t addr) {
    asm volatile("ldmatrix.sync.aligned.m8n8.x4.shared.b16 {%0,%1,%2,%3}, [%4];"
                 : "=r"(r[0]), "=r"(r[1]), "=r"(r[2]), "=r"(r[3]) : "r"(addr));
}
__device__ __forceinline__ void mma_bf16(float* d, const uint32_t* a,
                                         const uint32_t* b) {
    asm volatile(
        "mma.sync.aligned.m16n8k16.row.col.f32.bf16.bf16.f32 "
        "{%0,%1,%2,%3}, {%4,%5,%6,%7}, {%8,%9}, {%0,%1,%2,%3};"
        : "+f"(d[0]), "+f"(d[1]), "+f"(d[2]), "+f"(d[3])
        : "r"(a[0]), "r"(a[1]), "r"(a[2]), "r"(a[3]), "r"(b[0]), "r"(b[1]));
}
__device__ __forceinline__ void bsplit(float x, bf16& h, bf16& l) {
    h = __float2bfloat16_rn(x);
    l = __float2bfloat16_rn(x - __bfloat162float(h));
}

// ----------------------- GEMM: C = alpha * A.B^T ----------------------------
// CTA tile 128x128, BK=32, 128 threads, warp tile 64x64 (2m x 2n warps).
// OUTM=0: C f32. OUTM=1: split bf16 (C may carry inv-rowsum, mode bit3).
// OUTM=2: exp epilogue -> split bf16 P + per-(row,ntile) partial sums in C.
// mode bit0 (1): causal tile skip (n0 > m0); bit1 (2): causal K bound;
// bit2 (4): col+=64 if col>=128; bit3 (8): scale rows by C[row];
// bit4 (16): apply rope to cols with col%192>=128 (q epilogue);
// bit5 (32): reverse-m CTA order; bit6 (64): triangular-compacted grid.
#define ROWB 80
#define AT_B (128 * ROWB)                // 10240
#define BT_B (128 * ROWB)                // 10240
#define STG_B (2 * AT_B + 2 * BT_B)      // 40960
#define SMEM_BYTES (2 * STG_B)           // 81920 -> 2 CTAs/SM

__device__ __forceinline__ void load_tileA(uint32_t dst, const bf16* __restrict__ src,
                                           int ld, int k0, int tid) {
#pragma unroll
    for (int it = 0; it < 4; it++) {
        const int idx = tid + it * 128;
        const int row = idx >> 2, seg = idx & 3;
        cp16(dst + (uint32_t)(row * ROWB + seg * 16),
             src + (size_t)row * ld + k0 + seg * 8);
    }
}
__device__ __forceinline__ void load_tileB(uint32_t dst, const bf16* __restrict__ src,
                                           int ld, int k0, int limit, int tid) {
#pragma unroll
    for (int it = 0; it < 4; it++) {
        const int idx = tid + it * 128;
        const int row = idx >> 2, seg = idx & 3;
        const uint32_t d = dst + (uint32_t)(row * ROWB + seg * 16);
        if (row < limit) {
            cp16(d, src + (size_t)row * ld + k0 + seg * 8);
        } else {
            asm volatile("st.shared.v4.b32 [%0], {%1,%1,%1,%1};"
                         :: "r"(d), "r"(0) : "memory");
        }
    }
}
__device__ __forceinline__ void load_stage(uint32_t base,
                                           const bf16* Ath, const bf16* Atl,
                                           const bf16* Bth, const bf16* Btl,
                                           int lda, int ldb, int k0, int nlim, int tid) {
    load_tileA(base,                Ath, lda, k0, tid);
    load_tileA(base + AT_B,         Atl, lda, k0, tid);
    load_tileB(base + 2 * AT_B,        Bth, ldb, k0, nlim, tid);
    load_tileB(base + 2 * AT_B + BT_B, Btl, ldb, k0, nlim, tid);
}

template <int OUTM>
__global__ void __launch_bounds__(128)
gemm_bf3(const bf16* __restrict__ Ah, const bf16* __restrict__ Al,
         const bf16* __restrict__ Bh, const bf16* __restrict__ Bl,
         float* __restrict__ C, bf16* __restrict__ Ch, bf16* __restrict__ Cl,
         const float* __restrict__ fcos_, const float* __restrict__ fsin_,
         int M, int N, int K, int lda, int ldb, int ldc,
         long sAo, long sAi, long sBo, long sBi, long sCo, long sCi,
         int inner, float alpha, int mode)
{
    int m0, n0;
    if (mode & 64) {
        // triangular-compacted grid: blockIdx.x in [0, NTRI)
        const int T = blockIdx.x;
        int mi = (int)((sqrtf(8.f * (float)T + 1.f) - 1.f) * 0.5f);
        while ((mi + 1) * (mi + 2) / 2 <= T) mi++;
        while (mi * (mi + 1) / 2 > T) mi--;
        const int ni = T - mi * (mi + 1) / 2;
        m0 = mi * 128; n0 = ni * 128;
    } else {
        const int bx = (mode & 32) ? ((int)gridDim.x - 1 - (int)blockIdx.x)
                                   : (int)blockIdx.x;
        m0 = bx * 128; n0 = blockIdx.y * 128;
        if ((mode & 1) && n0 > m0) return;
    }

    extern __shared__ char smem[];
    __shared__ float sred[2][128];
    const uint32_t sb = smem_u32(smem);
    const int tid = threadIdx.x, lane = tid & 31, wid = tid >> 5;
    const int wm = wid >> 1, wn = wid & 1;
    const int g = lane >> 2, tig = lane & 3;

    const int z = blockIdx.z, zo = z / inner, zi = z - zo * inner;
    const long ofA = (long)zo * sAo + (long)zi * sAi;
    const long ofB = (long)zo * sBo + (long)zi * sBi;
    const long ofC = (long)zo * sCo + (long)zi * sCi;
    Ah += ofA; Al += ofA;
    Bh += ofB; Bl += ofB;

    const bf16* Ath = Ah + (size_t)m0 * lda;
    const bf16* Atl = Al + (size_t)m0 * lda;
    const bf16* Bth = Bh + (size_t)n0 * ldb;
    const bf16* Btl = Bl + (size_t)n0 * ldb;
    const int nlim = min(128, N - n0);

    float acc[4][8][4];
#pragma unroll
    for (int i = 0; i < 4; i++)
#pragma unroll
        for (int j = 0; j < 8; j++)
#pragma unroll
            for (int r = 0; r < 4; r++) acc[i][j][r] = 0.f;

    const int Keff = (mode & 2) ? min(K, m0 + 128) : K;
    const int nch = Keff >> 5;

    load_stage(sb, Ath, Atl, Bth, Btl, lda, ldb, 0, nlim, tid);
    CP_COMMIT();

    const uint32_t aoffL = (uint32_t)((wm * 64 + (lane & 15)) * ROWB + (lane >> 4) * 16);
    const uint32_t boffL = (uint32_t)((wn * 64 + ((lane >> 4) & 1) * 8 + (lane & 7)) * ROWB
                                      + ((lane >> 3) & 1) * 16);

    for (int c = 0; c < nch; c++) {
        if (c + 1 < nch) {
            load_stage(sb + ((c + 1) & 1) * STG_B, Ath, Atl, Bth, Btl,
                       lda, ldb, (c + 1) << 5, nlim, tid);
            CP_COMMIT();
            CP_WAIT(1);
        } else {
            CP_WAIT(0);
        }
        __syncthreads();

        const uint32_t base = sb + (c & 1) * STG_B;
        const uint32_t aA = base + aoffL;
        const uint32_t bA = base + 2 * AT_B + boffL;

#pragma unroll
        for (int ks = 0; ks < 2; ks++) {
            uint32_t bh[4][4], bl[4][4];
#pragma unroll
            for (int jj = 0; jj < 4; jj++) {
                ldm_x4(bh[jj], bA + ks * 32 + jj * 16 * ROWB);
                ldm_x4(bl[jj], bA + BT_B + ks * 32 + jj * 16 * ROWB);
            }
#pragma unroll
            for (int i = 0; i < 4; i++) {
                uint32_t ahf[4], alf[4];
                ldm_x4(ahf, aA + ks * 32 + i * 16 * ROWB);
                ldm_x4(alf, aA + AT_B + ks * 32 + i * 16 * ROWB);
#pragma unroll
                for (int j = 0; j < 8; j++) {
                    const uint32_t* bhp = &bh[j >> 1][(j & 1) * 2];
                    const uint32_t* blp = &bl[j >> 1][(j & 1) * 2];
                    mma_bf16(acc[i][j], alf, bhp);
                    mma_bf16(acc[i][j], ahf, blp);
                    mma_bf16(acc[i][j], ahf, bhp);
                }
            }
        }
        __syncthreads();
    }

    if (OUTM == 2) {
        // exp epilogue: unnormalized softmax numerators + deterministic
        // per-(row, n-tile) partial sums. M == SEQ; r0 is the s index.
        float* ps = C + (size_t)z * SEQ * 16;
        const int ntile = n0 >> 7;
#pragma unroll
        for (int i = 0; i < 4; i++) {
            const int r0 = m0 + wm * 64 + i * 16 + g;
            float s0 = 0.f, s1 = 0.f;
#pragma unroll
            for (int j = 0; j < 8; j++) {
                const int col = n0 + wn * 64 + j * 8 + tig * 2;
                const float e0 = (col     <= r0)     ? __expf(alpha * acc[i][j][0]) : 0.f;
                const float e1 = (col + 1 <= r0)     ? __expf(alpha * acc[i][j][1]) : 0.f;
                const float e2 = (col     <= r0 + 8) ? __expf(alpha * acc[i][j][2]) : 0.f;
                const float e3 = (col + 1 <= r0 + 8) ? __expf(alpha * acc[i][j][3]) : 0.f;
                s0 += e0 + e1; s1 += e2 + e3;
                bf16 h0, l0, h1, l1, h2, l2, h3, l3;
                bsplit(e0, h0, l0); bsplit(e1, h1, l1);
                bsplit(e2, h2, l2); bsplit(e3, h3, l3);
                *reinterpret_cast<__nv_bfloat162*>(Ch + ofC + (size_t)r0 * ldc + col)
                    = __nv_bfloat162(h0, h1);
                *reinterpret_cast<__nv_bfloat162*>(Cl + ofC + (size_t)r0 * ldc + col)
                    = __nv_bfloat162(l0, l1);
                *reinterpret_cast<__nv_bfloat162*>(Ch + ofC + (size_t)(r0 + 8) * ldc + col)
                    = __nv_bfloat162(h2, h3);
                *reinterpret_cast<__nv_bfloat162*>(Cl + ofC + (size_t)(r0 + 8) * ldc + col)
                    = __nv_bfloat162(l2, l3);
            }
            s0 += __shfl_xor_sync(0xffffffffu, s0, 1);
            s0 += __shfl_xor_sync(0xffffffffu, s0, 2);
            s1 += __shfl_xor_sync(0xffffffffu, s1, 1);
            s1 += __shfl_xor_sync(0xffffffffu, s1, 2);
            if (tig == 0) {
                sred[wn][wm * 64 + i * 16 + g]     = s0;
                sred[wn][wm * 64 + i * 16 + g + 8] = s1;
            }
        }
        __syncthreads();
        ps[(size_t)(m0 + tid) * 16 + ntile] = sred[0][tid] + sred[1][tid];
        return;
    }

    // standard epilogues
#pragma unroll
    for (int i = 0; i < 4; i++) {
        const int r0 = m0 + wm * 64 + i * 16 + g;
        float sc0 = alpha, sc1 = alpha;
        if (OUTM == 1 && (mode & 8)) {
            const float* invp = C + (size_t)z * SEQ;
            sc0 = invp[r0]; sc1 = invp[r0 + 8];
        }
#pragma unroll
        for (int j = 0; j < 8; j++) {
            const int col = n0 + wn * 64 + j * 8 + tig * 2;
            if (col >= N) continue;
            const int ocol = ((mode & 4) && col >= 128) ? col + 64 : col;
            float c0 = sc0 * acc[i][j][0], c1 = sc0 * acc[i][j][1];
            float c2 = sc1 * acc[i][j][2], c3 = sc1 * acc[i][j][3];
            if (OUTM == 1 && (mode & 16)) {
                // fused q rope: cols with col%192 >= 128 are rope pairs
                const int och = col % QK_HEAD;
                if (och >= NOPE) {
                    const int ii = (och - NOPE) >> 1;
                    const int p0 = r0 & (SEQ - 1);
                    const int p1 = (r0 + 8) & (SEQ - 1);
                    const float cc0 = fcos_[p0 * 32 + ii], ss0 = fsin_[p0 * 32 + ii];
                    const float cc1 = fcos_[p1 * 32 + ii], ss1 = fsin_[p1 * 32 + ii];
                    const float r00 = c0 * cc0 - c1 * ss0;
                    const float r01 = c0 * ss0 + c1 * cc0;
                    const float r10 = c2 * cc1 - c3 * ss1;
                    const float r11 = c2 * ss1 + c3 * cc1;
                    c0 = r00; c1 = r01; c2 = r10; c3 = r11;
                }
            }
            if (OUTM == 0) {
                float* p0 = C + ofC + (size_t)r0 * ldc + ocol;
                float* p1 = C + ofC + (size_t)(r0 + 8) * ldc + ocol;
                if (col + 1 < N) {
                    *reinterpret_cast<float2*>(p0) = make_float2(c0, c1);
                    *reinterpret_cast<float2*>(p1) = make_float2(c2, c3);
                } else { p0[0] = c0; p1[0] = c2; }
            } else {
                bf16 h0, l0, h1, l1, h2, l2, h3, l3;
                bsplit(c0, h0, l0); bsplit(c1, h1, l1);
                bsplit(c2, h2, l2); bsplit(c3, h3, l3);
                *reinterpret_cast<__nv_bfloat162*>(Ch + ofC + (size_t)r0 * ldc + ocol)
                    = __nv_bfloat162(h0, h1);
                *reinterpret_cast<__nv_bfloat162*>(Cl + ofC + (size_t)r0 * ldc + ocol)
                    = __nv_bfloat162(l0, l1);
                *reinterpret_cast<__nv_bfloat162*>(Ch + ofC + (size_t)(r0 + 8) * ldc + ocol)
                    = __nv_bfloat162(h2, h3);
                *reinterpret_cast<__nv_bfloat162*>(Cl + ofC + (size_t)(r0 + 8) * ldc + ocol)
                    = __nv_bfloat162(l2, l3);
            }
        }
    }
}

// ----------------- combine partial sums -> inverse row sums -----------------
__global__ void __launch_bounds__(256)
rowsum_combine_kernel()
{
    const long row = (long)blockIdx.x * 256 + threadIdx.x;  // [bh][s]
    const int s = (int)(row & (SEQ - 1));
    const int nt = (s >> 7) + 1;
    const float* ps = g_ps + row * 16;
    float sum = 0.f;
    for (int j = 0; j < nt; j++) sum += ps[j];
    g_inv[row] = 1.0f / sum;
}

// ---------------------- elementwise split f32 -> bf16 hi/lo ------------------
__global__ void __launch_bounds__(256)
split_kernel(const float* __restrict__ src, bf16* __restrict__ h,
             bf16* __restrict__ l, long n4)
{
    const long stride = (long)gridDim.x * blockDim.x;
    for (long i = blockIdx.x * (long)blockDim.x + threadIdx.x; i < n4; i += stride) {
        const float4 v = reinterpret_cast<const float4*>(src)[i];
        bf16 h0, l0, h1, l1, h2, l2, h3, l3;
        bsplit(v.x, h0, l0); bsplit(v.y, h1, l1);
        bsplit(v.z, h2, l2); bsplit(v.w, h3, l3);
        reinterpret_cast<__nv_bfloat162*>(h)[i * 2]     = __nv_bfloat162(h0, h1);
        reinterpret_cast<__nv_bfloat162*>(h)[i * 2 + 1] = __nv_bfloat162(h2, h3);
        reinterpret_cast<__nv_bfloat162*>(l)[i * 2]     = __nv_bfloat162(l0, l1);
        reinterpret_cast<__nv_bfloat162*>(l)[i * 2 + 1] = __nv_bfloat162(l2, l3);
    }
}

// ------------------- dual bf16 transpose (32x32 tiles) ----------------------
__global__ void __launch_bounds__(256)
transpose_bf2(const bf16* __restrict__ sh, const bf16* __restrict__ sl,
              bf16* __restrict__ dh, bf16* __restrict__ dl,
              int lds, int ldd, long sS, long sD)
{
    __shared__ float th[32][33], tl[32][33];
    const int z = blockIdx.z;
    sh += (long)z * sS; sl += (long)z * sS;
    dh += (long)z * sD; dl += (long)z * sD;
    const int r0 = blockIdx.x * 32, c0 = blockIdx.y * 32;
    const int tx = threadIdx.x, ty = threadIdx.y;
#pragma unroll
    for (int i = 0; i < 4; i++) {
        const long s = (long)(r0 + ty + 8 * i) * lds + c0 + tx;
        th[ty + 8 * i][tx] = __bfloat162float(sh[s]);
        tl[ty + 8 * i][tx] = __bfloat162float(sl[s]);
    }
    __syncthreads();
#pragma unroll
    for (int i = 0; i < 4; i++) {
        const long d = (long)(c0 + ty + 8 * i) * ldd + r0 + tx;
        dh[d] = __float2bfloat16_rn(th[tx][ty + 8 * i]);
        dl[d] = __float2bfloat16_rn(tl[tx][ty + 8 * i]);
    }
}

// --------------------------- rmsnorm: f32 -> split --------------------------
__global__ void __launch_bounds__(256)
rmsnorm_qa_kernel(const float* __restrict__ w)
{
    const long row = blockIdx.x;
    const float* p = g_qakv_f + row * NCOMB;
    const int tid = threadIdx.x;
    float v[6];
    float ss = 0.f;
#pragma unroll
    for (int i = 0; i < 6; i++) { v[i] = p[tid + i * 256]; ss += v[i] * v[i]; }
    __shared__ float red[256];
    red[tid] = ss; __syncthreads();
    for (int o = 128; o > 0; o >>= 1) {
        if (tid < o) red[tid] += red[tid + o];
        __syncthreads();
    }
    const float scale = rsqrtf(red[0] / (float)Q_LORA + EPS_F);
#pragma unroll
    for (int i = 0; i < 6; i++) {
        const int c = tid + i * 256;
        bf16 h, l;
        bsplit(v[i] * scale * w[c], h, l);
        g_qah[row * Q_LORA + c] = h;
        g_qal[row * Q_LORA + c] = l;
    }
}

// ------------- kv_process: qakv cols 1536:2112 -> split kf + rope broadcast --
__global__ void __launch_bounds__(256)
kv_process_kernel(const float* __restrict__ kv_norm_w,
                  const float* __restrict__ fcos,
                  const float* __restrict__ fsin)
{
    const long row = blockIdx.x;
    const int b = (int)(row >> 11);
    const int pos = (int)(row & (SEQ - 1));
    const float* src = g_qakv_f + row * NCOMB + Q_LORA;
    const int tid = threadIdx.x;

    __shared__ float red[256];
    __shared__ bf16 rh[ROPE], rl[ROPE];

    const float v0 = src[tid], v1 = src[tid + 256];
    red[tid] = v0 * v0 + v1 * v1; __syncthreads();
    for (int o = 128; o > 0; o >>= 1) {
        if (tid < o) red[tid] += red[tid + o];
        __syncthreads();
    }
    const float scale = rsqrtf(red[0] / (float)KV_LORA + EPS_F);
    bf16 h, l;
    bsplit(v0 * scale * kv_norm_w[tid], h, l);
    g_kfh[row * QKD + tid] = h; g_kfl[row * QKD + tid] = l;
    bsplit(v1 * scale * kv_norm_w[tid + 256], h, l);
    g_kfh[row * QKD + tid + 256] = h; g_kfl[row * QKD + tid + 256] = l;

    if (tid < 32) {
        const float x0 = src[KV_LORA + 2 * tid];
        const float x1 = src[KV_LORA + 2 * tid + 1];
        const float c = fcos[pos * 32 + tid];
        const float s = fsin[pos * 32 + tid];
        bsplit(x0 * c - x1 * s, h, l);
        rh[2 * tid] = h; rl[2 * tid] = l;
        bsplit(x0 * s + x1 * c, h, l);
        rh[2 * tid + 1] = h; rl[2 * tid + 1] = l;
    }
    __syncthreads();

    // broadcast rope into kve cols 128:192 for all heads
#pragma unroll
    for (int it = 0; it < 4; it++) {
        const int e = tid + it * 256;
        const int hd = e >> 6, j = e & 63;
        const size_t dst = ((size_t)(b * N_HEADS + hd) * SEQ + pos) * KVW + NOPE + j;
        g_kveh[dst] = rh[j];
        g_kvel[dst] = rl[j];
    }
}

// ---------------------------------------------------------------------------
extern "C" void kernel_launch(void* const* d_in, const int* in_sizes, int n_in,
                              void* d_out, int out_size)
{
    const float* x         = (const float*)d_in[0];
    const float* fcos      = (const float*)d_in[1];
    const float* fsin      = (const float*)d_in[2];
    // d_in[3] = mask (unused; causal mask computed inline, exact)
    const float* wq_a      = (const float*)d_in[4];
    const float* q_norm_w  = (const float*)d_in[5];
    const float* wq_b      = (const float*)d_in[6];
    const float* wkv_a     = (const float*)d_in[7];
    const float* kv_norm_w = (const float*)d_in[8];
    const float* wkv_b     = (const float*)d_in[9];
    const float* wo        = (const float*)d_in[10];
    float* out = (float*)d_out;

    bf16 *xh, *xl, *wch, *wcl, *wqbh, *wqbl, *wkvbh, *wkvbl, *woh, *wol;
    bf16 *qah, *qal, *qh, *ql, *kfh, *kfl, *kveh, *kvel, *vTh, *vTl;
    bf16 *Ph, *Pl, *o2h, *o2l;
    float *qakvf, *ps, *inv;
    cudaGetSymbolAddress((void**)&xh, g_xh);       cudaGetSymbolAddress((void**)&xl, g_xl);
    cudaGetSymbolAddress((void**)&wch, g_wcombh);  cudaGetSymbolAddress((void**)&wcl, g_wcombl);
    cudaGetSymbolAddress((void**)&wqbh, g_wqbh);   cudaGetSymbolAddress((void**)&wqbl, g_wqbl);
    cudaGetSymbolAddress((void**)&wkvbh, g_wkvbh); cudaGetSymbolAddress((void**)&wkvbl, g_wkvbl);
    cudaGetSymbolAddress((void**)&woh, g_woh);     cudaGetSymbolAddress((void**)&wol, g_wol);
    cudaGetSymbolAddress((void**)&qakvf, g_qakv_f);
    cudaGetSymbolAddress((void**)&qah, g_qah);     cudaGetSymbolAddress((void**)&qal, g_qal);
    cudaGetSymbolAddress((void**)&qh, g_qh);       cudaGetSymbolAddress((void**)&ql, g_ql);
    cudaGetSymbolAddress((void**)&kfh, g_kfh);     cudaGetSymbolAddress((void**)&kfl, g_kfl);
    cudaGetSymbolAddress((void**)&kveh, g_kveh);   cudaGetSymbolAddress((void**)&kvel, g_kvel);
    cudaGetSymbolAddress((void**)&vTh, g_vTh);     cudaGetSymbolAddress((void**)&vTl, g_vTl);
    cudaGetSymbolAddress((void**)&Ph, g_Ph);       cudaGetSymbolAddress((void**)&Pl, g_Pl);
    cudaGetSymbolAddress((void**)&ps, g_ps);       cudaGetSymbolAddress((void**)&inv, g_inv);
    cudaGetSymbolAddress((void**)&o2h, g_o2h);     cudaGetSymbolAddress((void**)&o2l, g_o2l);

    cudaFuncSetAttribute(gemm_bf3<0>, cudaFuncAttributeMaxDynamicSharedMemorySize, SMEM_BYTES);
    cudaFuncSetAttribute(gemm_bf3<1>, cudaFuncAttributeMaxDynamicSharedMemorySize, SMEM_BYTES);
    cudaFuncSetAttribute(gemm_bf3<2>, cudaFuncAttributeMaxDynamicSharedMemorySize, SMEM_BYTES);

    dim3 blk(256);
    dim3 gblk(128);
    dim3 tb(32, 8);

    // 0. split inputs + weights
    auto splits = [&](const float* s, bf16* h, bf16* l, long n) {
        const long n4 = n / 4;
        int gs = (int)min((n4 + 255) / 256, (long)4096);
        split_kernel<<<gs, blk>>>(s, h, l, n4);
    };
    splits(x,     xh,  xl,  (long)ROWS * DIM);
    splits(wq_a,  wch, wcl, (long)Q_LORA * DIM);
    splits(wkv_a, wch + (size_t)Q_LORA * DIM, wcl + (size_t)Q_LORA * DIM,
           (long)QKD * DIM);
    splits(wq_b,  wqbh, wqbl, (long)N_HEADS * QK_HEAD * Q_LORA);
    splits(wkv_b, wkvbh, wkvbl, (long)N_HEADS * 256 * KV_LORA);
    splits(wo,    woh,  wol,  (long)DIM * DIM);

    // 1. qakv = x @ [wq_a ; wkv_a]^T  (merged, f32 out)
    gemm_bf3<0><<<dim3(ROWS/128, (NCOMB + 127)/128, 1), gblk, SMEM_BYTES>>>(
        xh, xl, wch, wcl, qakvf, nullptr, nullptr, nullptr, nullptr,
        ROWS, NCOMB, DIM, DIM, DIM, NCOMB, 0,0, 0,0, 0,0, 1, 1.f, 0);

    // 2. norms (+ k rope broadcast into kve)
    rmsnorm_qa_kernel<<<ROWS, blk>>>(q_norm_w);
    kv_process_kernel<<<ROWS, blk>>>(kv_norm_w, fcos, fsin);

    // 3. q = qa @ wq_b^T  (split out, rope fused into epilogue)
    gemm_bf3<1><<<dim3(ROWS/128, (N_HEADS*QK_HEAD)/128, 1), gblk, SMEM_BYTES>>>(
        qah, qal, wqbh, wqbl, nullptr, qh, ql, fcos, fsin,
        ROWS, N_HEADS*QK_HEAD, Q_LORA, Q_LORA, Q_LORA, N_HEADS*QK_HEAD,
        0,0, 0,0, 0,0, 1, 1.f, 16);

    // 4. kve = kf_c @ wkvb^T  (merged k/v, split out, col shift)
    gemm_bf3<1><<<dim3(SEQ/128, 2, NBH), gblk, SMEM_BYTES>>>(
        kfh, kfl, wkvbh, wkvbl, nullptr, kveh, kvel, nullptr, nullptr,
        SEQ, 256, KV_LORA, QKD, KV_LORA, KVW,
        (long)SEQ*QKD, 0,
        0, (long)256*KV_LORA,
        (long)N_HEADS*SEQ*KVW, (long)SEQ*KVW,
        N_HEADS, 1.f, 4);

    // 5. transpose v (kve cols 192:320) -> vT
    transpose_bf2<<<dim3(SEQ/32, V_HEAD/32, NBH), tb>>>(
        kveh + 192, kvel + 192, vTh, vTl, KVW, SEQ,
        (long)SEQ*KVW, (long)V_HEAD*SEQ);

    // 6. P~ = exp(SCALE * q'.kve^T)  (triangular-compacted grid)
    gemm_bf3<2><<<dim3(NTRI, 1, NBH), gblk, SMEM_BYTES>>>(
        qh, ql, kveh, kvel, ps, Ph, Pl, nullptr, nullptr,
        SEQ, SEQ, QK_HEAD, N_HEADS*QK_HEAD, KVW, SEQ,
        (long)SEQ*N_HEADS*QK_HEAD, QK_HEAD,
        (long)N_HEADS*SEQ*KVW, (long)SEQ*KVW,
        (long)N_HEADS*SEQ*SEQ, (long)SEQ*SEQ,
        N_HEADS, SCALE_F, 64);

    // 7. inverse row sums (deterministic fixed-order combine)
    rowsum_combine_kernel<<<NBH*SEQ/256, blk>>>();

    // 8. o2 = (P~ @ vT^T) * inv_rowsum  (causal K bound, longest-first order)
    gemm_bf3<1><<<dim3(SEQ/128, 1, NBH), gblk, SMEM_BYTES>>>(
        Ph, Pl, vTh, vTl, inv, o2h, o2l, nullptr, nullptr,
        SEQ, V_HEAD, SEQ, SEQ, SEQ, DIM,
        (long)N_HEADS*SEQ*SEQ, (long)SEQ*SEQ,
        (long)N_HEADS*V_HEAD*SEQ, (long)V_HEAD*SEQ,
        (long)SEQ*DIM, V_HEAD,
        N_HEADS, 1.f, 2 | 8 | 32);

    // 9. out = o2 @ wo^T  (f32 out)
    gemm_bf3<0><<<dim3(ROWS/128, DIM/128, 1), gblk, SMEM_BYTES>>>(
        o2h, o2l, woh, wol, out, nullptr, nullptr, nullptr, nullptr,
        ROWS, DIM, DIM, DIM, DIM, DIM, 0,0, 0,0, 0,0, 1, 1.f, 0);
}